// round 7
// baseline (speedup 1.0000x reference)
#include <cuda_runtime.h>
#include <cstdint>

#define P    1024
#define RDIM 128
#define MDIM 128

#define JS   8                       // j-splits in GEMM
#define RPB  16                      // rows per GEMM block

// Scratch (device globals — allocation-free).
__device__ __align__(16) float g_wbuf[P * P];            // softmax weights, 4 MB
__device__ __align__(16) float g_part[JS * P * MDIM];    // split-K partials, 4 MB

// =====================================================================
// Kernel A (R5 winner, unchanged): one block per output row i.
//   scores[j] = rela[i,j,:] . att_w  (8 warps x 128 j, 8-row pipeline)
//   then in-block masked softmax -> g_wbuf[i, :]
// =====================================================================
__global__ __launch_bounds__(256)
void si_row_kernel(const float* __restrict__ rela,
                   const int*   __restrict__ nei,
                   const float* __restrict__ att_w,
                   const float* __restrict__ att_b,
                   float*       __restrict__ wout)
{
    __shared__ float s_sc[P];
    __shared__ int   s_nei[P];
    __shared__ float s_red[16];

    const int tid  = threadIdx.x;
    const int lane = tid & 31;
    const int warp = tid >> 5;
    const int i    = blockIdx.x;

    {
        const int4 nv = reinterpret_cast<const int4*>(nei + (size_t)i * P)[tid];
        reinterpret_cast<int4*>(s_nei)[tid] = nv;
    }

    const float4 w4 = reinterpret_cast<const float4*>(att_w)[lane];
    const float* base = rela + ((size_t)i * P + (size_t)warp * 128) * RDIM;

    float4 cur[8], nxt[8];
    #pragma unroll
    for (int k = 0; k < 8; k++)
        cur[k] = reinterpret_cast<const float4*>(base + (size_t)k * RDIM)[lane];

    #pragma unroll 1
    for (int it = 0; it < 16; it++) {
        if (it < 15) {
            const float* nb = base + (size_t)(it + 1) * 8 * RDIM;
            #pragma unroll
            for (int k = 0; k < 8; k++)
                nxt[k] = reinterpret_cast<const float4*>(nb + (size_t)k * RDIM)[lane];
        }

        float d[8];
        #pragma unroll
        for (int k = 0; k < 8; k++)
            d[k] = fmaf(cur[k].x, w4.x,
                   fmaf(cur[k].y, w4.y,
                   fmaf(cur[k].z, w4.z, cur[k].w * w4.w)));

        #pragma unroll
        for (int s = 16; s >= 4; s >>= 1) {
            #pragma unroll
            for (int k = 0; k < 8; k++)
                d[k] += __shfl_xor_sync(0xFFFFFFFFu, d[k], s);
        }
        const int g = lane >> 2;
        float v = d[0];
        v = (g == 1) ? d[1] : v;
        v = (g == 2) ? d[2] : v;
        v = (g == 3) ? d[3] : v;
        v = (g == 4) ? d[4] : v;
        v = (g == 5) ? d[5] : v;
        v = (g == 6) ? d[6] : v;
        v = (g == 7) ? d[7] : v;
        v += __shfl_xor_sync(0xFFFFFFFFu, v, 1);
        v += __shfl_xor_sync(0xFFFFFFFFu, v, 2);
        if ((lane & 3) == 0)
            s_sc[warp * 128 + it * 8 + g] = v;

        #pragma unroll
        for (int k = 0; k < 8; k++) cur[k] = nxt[k];
    }
    __syncthreads();

    const float b = att_b[0];

    float vals[4];
    unsigned mbits = 0;
    float vmax = -1e30f;
    #pragma unroll
    for (int k = 0; k < 4; k++) {
        const int j = tid + k * 256;
        const bool m = (s_nei[j] > 0);
        if (m) mbits |= (1u << k);
        const float v = m ? (s_sc[j] + b) : -1e-6f;
        vals[k] = v;
        vmax = fmaxf(vmax, v);
    }
    #pragma unroll
    for (int s = 16; s; s >>= 1)
        vmax = fmaxf(vmax, __shfl_xor_sync(0xFFFFFFFFu, vmax, s));
    if (lane == 0) s_red[warp] = vmax;
    __syncthreads();
    {
        float t = s_red[lane & 7];
        #pragma unroll
        for (int s = 4; s; s >>= 1)
            t = fmaxf(t, __shfl_xor_sync(0xFFFFFFFFu, t, s));
        vmax = t;
    }

    float vsum = 0.0f;
    #pragma unroll
    for (int k = 0; k < 4; k++) {
        const float e = __expf(vals[k] - vmax);
        vals[k] = e;
        vsum += e;
    }
    #pragma unroll
    for (int s = 16; s; s >>= 1)
        vsum += __shfl_xor_sync(0xFFFFFFFFu, vsum, s);
    __syncthreads();
    if (lane == 0) s_red[8 + warp] = vsum;
    __syncthreads();
    {
        float t = s_red[8 + (lane & 7)];
        #pragma unroll
        for (int s = 4; s; s >>= 1)
            t += __shfl_xor_sync(0xFFFFFFFFu, t, s);
        vsum = t;
    }
    const float inv = 1.0f / vsum;

    float* wrow = wout + (size_t)i * P;
    #pragma unroll
    for (int k = 0; k < 4; k++) {
        const int j = tid + k * 256;
        wrow[j] = ((mbits >> k) & 1u) ? vals[k] * inv : 0.0f;
    }
}

// =====================================================================
// Kernel B1: split-K GEMM partials with packed f32x2 FMA (FFMA2).
// Grid 512 = 64 i-tiles x 8 j-splits; 256 threads.
// Thread layout: m2 = tid & 63 (m-pair -> m = 2*m2, 2*m2+1),
//                sub = tid >> 6 (4 subs x 32 j each).
// Weights pre-duplicated in smem as {w,w} u64 pairs -> LDS.128 + FFMA2.
// =====================================================================
__device__ __forceinline__ void ffma2(unsigned long long& d,
                                      unsigned long long a,
                                      unsigned long long b)
{
    asm("fma.rn.f32x2 %0, %1, %2, %0;" : "+l"(d) : "l"(a), "l"(b));
}

__global__ __launch_bounds__(256)
void si_gemm_part_kernel(const float* __restrict__ hidden,
                         const float* __restrict__ wsrc,
                         float*       __restrict__ part)
{
    extern __shared__ unsigned char smem_raw[];
    unsigned long long* s_wd = reinterpret_cast<unsigned long long*>(smem_raw); // [RPB*128] {w,w} pairs, 16 KB
    float* s_part = reinterpret_cast<float*>(smem_raw + RPB * 128 * 8);         // [4*RPB*128] floats, 32 KB

    const int tid = threadIdx.x;
    const int it  = blockIdx.x >> 3;
    const int js  = blockIdx.x & 7;
    const int i0  = it * RPB;
    const int jb  = js * 128;

    // stage weights duplicated: 2048 scalars -> 2048 u64 pairs (8/thread)
    #pragma unroll
    for (int t = 0; t < 8; t++) {
        const int o = tid + t * 256;          // 0..2047
        const int r = o >> 7;
        const int jj = o & 127;
        const float w = wsrc[(size_t)(i0 + r) * P + jb + jj];
        float2 p; p.x = w; p.y = w;
        reinterpret_cast<float2*>(s_wd)[o] = p;
    }
    __syncthreads();

    {
        const int m2  = tid & 63;       // m pair index
        const int sub = tid >> 6;       // 0..3
        const int j0  = sub * 32;

        unsigned long long acc[RPB];
        #pragma unroll
        for (int r = 0; r < RPB; r++) acc[r] = 0ull;

        #pragma unroll 1
        for (int j = j0; j < j0 + 32; j += 4) {
            // 4 independent 8-byte hidden loads (m pair)
            unsigned long long hv[4];
            #pragma unroll
            for (int t = 0; t < 4; t++)
                hv[t] = *reinterpret_cast<const unsigned long long*>(
                    &hidden[(size_t)(jb + j + t) * MDIM + 2 * m2]);

            #pragma unroll
            for (int r = 0; r < RPB; r++) {
                const ulonglong2 w01 = *reinterpret_cast<const ulonglong2*>(&s_wd[r * 128 + j]);
                const ulonglong2 w23 = *reinterpret_cast<const ulonglong2*>(&s_wd[r * 128 + j + 2]);
                ffma2(acc[r], w01.x, hv[0]);
                ffma2(acc[r], w01.y, hv[1]);
                ffma2(acc[r], w23.x, hv[2]);
                ffma2(acc[r], w23.y, hv[3]);
            }
        }

        #pragma unroll
        for (int r = 0; r < RPB; r++) {
            unsigned lo, hi;
            asm("mov.b64 {%0, %1}, %2;" : "=r"(lo), "=r"(hi) : "l"(acc[r]));
            float2 f; f.x = __uint_as_float(lo); f.y = __uint_as_float(hi);
            *reinterpret_cast<float2*>(&s_part[(sub * RPB + r) * 128 + 2 * m2]) = f;
        }
    }
    __syncthreads();

    // combine the 4 subs, write partial: part[js][i0+r][m]
    #pragma unroll
    for (int t = 0; t < 8; t++) {
        const int o = tid + t * 256;          // 0..2047
        const int r = o >> 7;
        const int mm = o & 127;
        part[(size_t)js * P * MDIM + (size_t)(i0 + r) * MDIM + mm] =
            (s_part[o] + s_part[2048 + o]) + (s_part[4096 + o] + s_part[6144 + o]);
    }
}

// =====================================================================
// Kernel B2: reduce 8 split-K partials -> out. 131072 floats = 32768 f4.
// =====================================================================
__global__ __launch_bounds__(256)
void si_gemm_reduce_kernel(const float* __restrict__ part,
                           float*       __restrict__ out)
{
    const int e4 = blockIdx.x * 256 + threadIdx.x;
    const float4* p4 = reinterpret_cast<const float4*>(part);
    float4 s = p4[e4];
    #pragma unroll
    for (int k = 1; k < JS; k++) {
        const float4 a = p4[(size_t)k * 32768 + e4];
        s.x += a.x; s.y += a.y; s.z += a.z; s.w += a.w;
    }
    reinterpret_cast<float4*>(out)[e4] = s;
}

extern "C" void kernel_launch(void* const* d_in, const int* in_sizes, int n_in,
                              void* d_out, int out_size)
{
    (void)in_sizes; (void)n_in; (void)out_size;
    const float* hidden = (const float*)d_in[0];   // [1024,128]
    const float* rela   = (const float*)d_in[1];   // [1024,1024,128]
    // d_in[2] = corr_index : unused
    const int*   nei    = (const int*)  d_in[3];   // [1024,1024]
    const float* att_w  = (const float*)d_in[4];   // [128]
    const float* att_b  = (const float*)d_in[5];   // [1]
    float* out = (float*)d_out;                    // [1024,128] f32

    float* wbuf;  cudaGetSymbolAddress((void**)&wbuf, g_wbuf);
    float* pbuf;  cudaGetSymbolAddress((void**)&pbuf, g_part);

    const int b1_smem = RPB * 128 * 8 + 4 * RPB * 128 * 4;  // 16 KB + 32 KB
    cudaFuncSetAttribute(si_gemm_part_kernel,
                         cudaFuncAttributeMaxDynamicSharedMemorySize, b1_smem);

    si_row_kernel<<<P, 256>>>(rela, nei, att_w, att_b, wbuf);
    si_gemm_part_kernel<<<(P / RPB) * JS, 256, b1_smem>>>(hidden, wbuf, pbuf);
    si_gemm_reduce_kernel<<<P * MDIM / 4 / 256, 256>>>(pbuf, out);
}

// round 8
// speedup vs baseline: 1.0397x; 1.0397x over previous
#include <cuda_runtime.h>
#include <cstdint>

#define P    1024
#define RDIM 128
#define MDIM 128

#define JSPLIT 4                     // j-splits in GEMM
#define ITILE  32                    // rows per GEMM block

// Scratch (device globals — allocation-free).
__device__ __align__(16) float g_wbuf[P * P];               // softmax weights, 4 MB
__device__ __align__(16) float g_part[JSPLIT * P * MDIM];   // split-K partials, 2 MB

// =====================================================================
// Kernel A (R5 winner, unchanged): one block per output row i.
// =====================================================================
__global__ __launch_bounds__(256)
void si_row_kernel(const float* __restrict__ rela,
                   const int*   __restrict__ nei,
                   const float* __restrict__ att_w,
                   const float* __restrict__ att_b,
                   float*       __restrict__ wout)
{
    __shared__ float s_sc[P];
    __shared__ int   s_nei[P];
    __shared__ float s_red[16];

    const int tid  = threadIdx.x;
    const int lane = tid & 31;
    const int warp = tid >> 5;
    const int i    = blockIdx.x;

    {
        const int4 nv = reinterpret_cast<const int4*>(nei + (size_t)i * P)[tid];
        reinterpret_cast<int4*>(s_nei)[tid] = nv;
    }

    const float4 w4 = reinterpret_cast<const float4*>(att_w)[lane];
    const float* base = rela + ((size_t)i * P + (size_t)warp * 128) * RDIM;

    float4 cur[8], nxt[8];
    #pragma unroll
    for (int k = 0; k < 8; k++)
        cur[k] = reinterpret_cast<const float4*>(base + (size_t)k * RDIM)[lane];

    #pragma unroll 1
    for (int it = 0; it < 16; it++) {
        if (it < 15) {
            const float* nb = base + (size_t)(it + 1) * 8 * RDIM;
            #pragma unroll
            for (int k = 0; k < 8; k++)
                nxt[k] = reinterpret_cast<const float4*>(nb + (size_t)k * RDIM)[lane];
        }

        float d[8];
        #pragma unroll
        for (int k = 0; k < 8; k++)
            d[k] = fmaf(cur[k].x, w4.x,
                   fmaf(cur[k].y, w4.y,
                   fmaf(cur[k].z, w4.z, cur[k].w * w4.w)));

        #pragma unroll
        for (int s = 16; s >= 4; s >>= 1) {
            #pragma unroll
            for (int k = 0; k < 8; k++)
                d[k] += __shfl_xor_sync(0xFFFFFFFFu, d[k], s);
        }
        const int g = lane >> 2;
        float v = d[0];
        v = (g == 1) ? d[1] : v;
        v = (g == 2) ? d[2] : v;
        v = (g == 3) ? d[3] : v;
        v = (g == 4) ? d[4] : v;
        v = (g == 5) ? d[5] : v;
        v = (g == 6) ? d[6] : v;
        v = (g == 7) ? d[7] : v;
        v += __shfl_xor_sync(0xFFFFFFFFu, v, 1);
        v += __shfl_xor_sync(0xFFFFFFFFu, v, 2);
        if ((lane & 3) == 0)
            s_sc[warp * 128 + it * 8 + g] = v;

        #pragma unroll
        for (int k = 0; k < 8; k++) cur[k] = nxt[k];
    }
    __syncthreads();

    const float b = att_b[0];

    float vals[4];
    unsigned mbits = 0;
    float vmax = -1e30f;
    #pragma unroll
    for (int k = 0; k < 4; k++) {
        const int j = tid + k * 256;
        const bool m = (s_nei[j] > 0);
        if (m) mbits |= (1u << k);
        const float v = m ? (s_sc[j] + b) : -1e-6f;
        vals[k] = v;
        vmax = fmaxf(vmax, v);
    }
    #pragma unroll
    for (int s = 16; s; s >>= 1)
        vmax = fmaxf(vmax, __shfl_xor_sync(0xFFFFFFFFu, vmax, s));
    if (lane == 0) s_red[warp] = vmax;
    __syncthreads();
    {
        float t = s_red[lane & 7];
        #pragma unroll
        for (int s = 4; s; s >>= 1)
            t = fmaxf(t, __shfl_xor_sync(0xFFFFFFFFu, t, s));
        vmax = t;
    }

    float vsum = 0.0f;
    #pragma unroll
    for (int k = 0; k < 4; k++) {
        const float e = __expf(vals[k] - vmax);
        vals[k] = e;
        vsum += e;
    }
    #pragma unroll
    for (int s = 16; s; s >>= 1)
        vsum += __shfl_xor_sync(0xFFFFFFFFu, vsum, s);
    __syncthreads();
    if (lane == 0) s_red[8 + warp] = vsum;
    __syncthreads();
    {
        float t = s_red[8 + (lane & 7)];
        #pragma unroll
        for (int s = 4; s; s >>= 1)
            t += __shfl_xor_sync(0xFFFFFFFFu, t, s);
        vsum = t;
    }
    const float inv = 1.0f / vsum;

    float* wrow = wout + (size_t)i * P;
    #pragma unroll
    for (int k = 0; k < 4; k++) {
        const int j = tid + k * 256;
        wrow[j] = ((mbits >> k) & 1u) ? vals[k] * inv : 0.0f;
    }
}

// =====================================================================
// Kernel B1: tf32 tensor-core split-K GEMM.
// Grid 128 = 32 i-tiles x 4 j-splits; 256 threads (8 warps).
// Block (it, js): D[i0..i0+32) x m[0..128) over k (= j) in [jb, jb+256).
// W (A operand, 32x256) staged once in smem (tf32 bits, stride 260);
// H (B operand) staged in 64x128 chunks (tf32 bits, stride 136).
// Warp w: m-half = w>>2 (16 rows), n-block = (w&3)*32 (4 n-tiles of 8).
// =====================================================================
#define WSTRIDE 260
#define HSTRIDE 136
#define KCHUNK  64
#define B1_SMEM ((ITILE * WSTRIDE + KCHUNK * HSTRIDE) * 4)

__device__ __forceinline__ uint32_t f2tf32(float f) {
    uint32_t r;
    asm("cvt.rna.tf32.f32 %0, %1;" : "=r"(r) : "f"(f));
    return r;
}

__device__ __forceinline__ void mma_tf32(float d[4],
                                         uint32_t a0, uint32_t a1,
                                         uint32_t a2, uint32_t a3,
                                         uint32_t b0, uint32_t b1)
{
    asm("mma.sync.aligned.m16n8k8.row.col.f32.tf32.tf32.f32 "
        "{%0,%1,%2,%3}, {%4,%5,%6,%7}, {%8,%9}, {%0,%1,%2,%3};"
        : "+f"(d[0]), "+f"(d[1]), "+f"(d[2]), "+f"(d[3])
        : "r"(a0), "r"(a1), "r"(a2), "r"(a3), "r"(b0), "r"(b1));
}

__global__ __launch_bounds__(256)
void si_gemm_tc_kernel(const float* __restrict__ hidden,
                       const float* __restrict__ wsrc,
                       float*       __restrict__ part)
{
    extern __shared__ uint32_t smem_u[];
    uint32_t* s_w = smem_u;                      // [ITILE * WSTRIDE]
    uint32_t* s_h = smem_u + ITILE * WSTRIDE;    // [KCHUNK * HSTRIDE]

    const int tid  = threadIdx.x;
    const int lane = tid & 31;
    const int warp = tid >> 5;
    const int it   = blockIdx.x >> 2;            // 0..31
    const int js   = blockIdx.x & 3;             // 0..3
    const int i0   = it * ITILE;
    const int jb   = js * 256;

    // ---- stage W tile (32 x 256) once, converting to tf32 bits ----
    #pragma unroll
    for (int t = 0; t < 8; t++) {
        const int idx4 = tid + t * 256;          // 0..2047 float4s
        const int r    = idx4 >> 6;              // row (64 f4 per row)
        const int c4   = idx4 & 63;
        const float4 v = *reinterpret_cast<const float4*>(
            &wsrc[(size_t)(i0 + r) * P + jb + c4 * 4]);
        uint4 u;
        u.x = f2tf32(v.x); u.y = f2tf32(v.y);
        u.z = f2tf32(v.z); u.w = f2tf32(v.w);
        *reinterpret_cast<uint4*>(&s_w[r * WSTRIDE + c4 * 4]) = u;
    }

    const int g  = lane >> 2;       // groupID 0..7
    const int tg = lane & 3;        // thread-in-group 0..3
    const int mh = warp >> 2;       // m-half 0/1
    const int nb = (warp & 3) * 32; // n-block base

    float d[4][4];
    #pragma unroll
    for (int nt = 0; nt < 4; nt++)
        #pragma unroll
        for (int c = 0; c < 4; c++) d[nt][c] = 0.0f;

    #pragma unroll 1
    for (int kc = 0; kc < 256; kc += KCHUNK) {
        // ---- stage H chunk (64 x 128), tf32 bits ----
        __syncthreads();   // previous chunk fully consumed
        #pragma unroll
        for (int t = 0; t < 8; t++) {
            const int idx4 = tid + t * 256;      // 0..2047 float4s
            const int k    = idx4 >> 5;          // row (32 f4 per row)
            const int m4   = idx4 & 31;
            const float4 v = *reinterpret_cast<const float4*>(
                &hidden[(size_t)(jb + kc + k) * MDIM + m4 * 4]);
            uint4 u;
            u.x = f2tf32(v.x); u.y = f2tf32(v.y);
            u.z = f2tf32(v.z); u.w = f2tf32(v.w);
            *reinterpret_cast<uint4*>(&s_h[k * HSTRIDE + m4 * 4]) = u;
        }
        __syncthreads();

        // ---- 8 k-steps of m16n8k8 ----
        #pragma unroll
        for (int ks = 0; ks < 8; ks++) {
            const int kA = kc + ks * 8;          // col in s_w
            const int rowA = mh * 16 + g;
            const uint32_t a0 = s_w[(rowA    ) * WSTRIDE + kA + tg    ];
            const uint32_t a1 = s_w[(rowA + 8) * WSTRIDE + kA + tg    ];
            const uint32_t a2 = s_w[(rowA    ) * WSTRIDE + kA + tg + 4];
            const uint32_t a3 = s_w[(rowA + 8) * WSTRIDE + kA + tg + 4];

            const int kH = ks * 8;               // row in s_h
            #pragma unroll
            for (int nt = 0; nt < 4; nt++) {
                const int n = nb + nt * 8 + g;
                const uint32_t b0 = s_h[(kH + tg    ) * HSTRIDE + n];
                const uint32_t b1 = s_h[(kH + tg + 4) * HSTRIDE + n];
                mma_tf32(d[nt], a0, a1, a2, a3, b0, b1);
            }
        }
    }

    // ---- epilogue: write D fragments to split-K partial buffer ----
    {
        float* pb = part + (size_t)js * P * MDIM;
        const int r0 = i0 + mh * 16 + g;
        #pragma unroll
        for (int nt = 0; nt < 4; nt++) {
            const int col = nb + nt * 8 + 2 * tg;
            float2 lo; lo.x = d[nt][0]; lo.y = d[nt][1];
            float2 hi; hi.x = d[nt][2]; hi.y = d[nt][3];
            *reinterpret_cast<float2*>(&pb[(size_t)(r0    ) * MDIM + col]) = lo;
            *reinterpret_cast<float2*>(&pb[(size_t)(r0 + 8) * MDIM + col]) = hi;
        }
    }
}

// =====================================================================
// Kernel B2: reduce 4 split-K partials -> out. 131072 floats = 32768 f4.
// =====================================================================
__global__ __launch_bounds__(256)
void si_gemm_reduce_kernel(const float* __restrict__ part,
                           float*       __restrict__ out)
{
    const int e4 = blockIdx.x * 256 + threadIdx.x;   // 0..32767
    const float4* p4 = reinterpret_cast<const float4*>(part);
    const float4 a = p4[0 * 32768 + e4];
    const float4 b = p4[1 * 32768 + e4];
    const float4 c = p4[2 * 32768 + e4];
    const float4 e = p4[3 * 32768 + e4];
    float4 s;
    s.x = (a.x + b.x) + (c.x + e.x);
    s.y = (a.y + b.y) + (c.y + e.y);
    s.z = (a.z + b.z) + (c.z + e.z);
    s.w = (a.w + b.w) + (c.w + e.w);
    reinterpret_cast<float4*>(out)[e4] = s;
}

extern "C" void kernel_launch(void* const* d_in, const int* in_sizes, int n_in,
                              void* d_out, int out_size)
{
    (void)in_sizes; (void)n_in; (void)out_size;
    const float* hidden = (const float*)d_in[0];   // [1024,128]
    const float* rela   = (const float*)d_in[1];   // [1024,1024,128]
    // d_in[2] = corr_index : unused
    const int*   nei    = (const int*)  d_in[3];   // [1024,1024]
    const float* att_w  = (const float*)d_in[4];   // [128]
    const float* att_b  = (const float*)d_in[5];   // [1]
    float* out = (float*)d_out;                    // [1024,128] f32

    float* wbuf;  cudaGetSymbolAddress((void**)&wbuf, g_wbuf);
    float* pbuf;  cudaGetSymbolAddress((void**)&pbuf, g_part);

    cudaFuncSetAttribute(si_gemm_tc_kernel,
                         cudaFuncAttributeMaxDynamicSharedMemorySize, B1_SMEM);

    si_row_kernel<<<P, 256>>>(rela, nei, att_w, att_b, wbuf);
    si_gemm_tc_kernel<<<(P / ITILE) * JSPLIT, 256, B1_SMEM>>>(hidden, wbuf, pbuf);
    si_gemm_reduce_kernel<<<P * MDIM / 4 / 256, 256>>>(pbuf, out);
}

// round 9
// speedup vs baseline: 1.1286x; 1.0855x over previous
#include <cuda_runtime.h>
#include <cstdint>

#define P    1024
#define RDIM 128
#define MDIM 128

#define JSPLIT 4                     // j-splits in GEMM
#define ITILE  32                    // rows per GEMM block

// Scratch (device globals — allocation-free).
__device__ __align__(16) float g_wbuf[P * P];               // softmax weights, 4 MB
__device__ __align__(16) float g_part[JSPLIT * P * MDIM];   // split-K partials, 2 MB

// =====================================================================
// Kernel A: one block per output row i, 8 warps x 128 j each.
// Per-warp 3-stage cp.async pipeline: global -> smem chunks of 8 rows
// (4 KB), 12 KB in flight per warp, no cross-warp syncs in the stream.
// Then in-block masked softmax -> g_wbuf[i, :].
// smem ~104 KB  => 2 CTAs/SM.
// =====================================================================
#define STAGES 3
#define A_SMEM_FLOATS (8 * STAGES * 1024 + 1024 + 1024 + 16)
#define A_SMEM_BYTES  (A_SMEM_FLOATS * 4)

__device__ __forceinline__ void cp16(uint32_t dst, const float* src) {
    asm volatile("cp.async.cg.shared.global [%0], [%1], 16;"
                 :: "r"(dst), "l"(src) : "memory");
}

__global__ __launch_bounds__(256)
void si_row_kernel(const float* __restrict__ rela,
                   const int*   __restrict__ nei,
                   const float* __restrict__ att_w,
                   const float* __restrict__ att_b,
                   float*       __restrict__ wout)
{
    extern __shared__ float smem[];
    float* s_buf = smem;                               // 8 * STAGES * 1024
    float* s_sc  = smem + 8 * STAGES * 1024;           // 1024
    int*   s_nei = (int*)(s_sc + 1024);                // 1024
    float* s_red = (float*)(s_nei + 1024);             // 16

    const int tid  = threadIdx.x;
    const int lane = tid & 31;
    const int warp = tid >> 5;
    const int i    = blockIdx.x;

    // prefetch nei row (overlaps the big stream)
    {
        const int4 nv = reinterpret_cast<const int4*>(nei + (size_t)i * P)[tid];
        reinterpret_cast<int4*>(s_nei)[tid] = nv;
    }

    const float4 w4 = reinterpret_cast<const float4*>(att_w)[lane];

    // warp w owns j in [w*128, (w+1)*128): 16 iters x 8 rows
    const float* base  = rela + ((size_t)i * P + (size_t)warp * 128) * RDIM;
    float* wslab = s_buf + warp * (STAGES * 1024);
    const uint32_t sbase = (uint32_t)__cvta_generic_to_shared(wslab);

    // prologue: fill 3 stages
    #pragma unroll
    for (int s = 0; s < STAGES; s++) {
        const float* gp = base + (size_t)s * 8 * RDIM + lane * 4;
        const uint32_t dst = sbase + s * 4096 + lane * 16;
        #pragma unroll
        for (int k = 0; k < 8; k++)
            cp16(dst + k * 512, gp + k * RDIM);
        asm volatile("cp.async.commit_group;" ::: "memory");
    }

    int slot = 0;
    #pragma unroll 1
    for (int it = 0; it < 16; it++) {
        asm volatile("cp.async.wait_group %0;" :: "n"(STAGES - 1) : "memory");
        __syncwarp();

        const float* sb = wslab + slot * 1024;
        float d[8];
        #pragma unroll
        for (int k = 0; k < 8; k++) {
            const float4 a = *reinterpret_cast<const float4*>(sb + k * 128 + lane * 4);
            d[k] = fmaf(a.x, w4.x,
                   fmaf(a.y, w4.y,
                   fmaf(a.z, w4.z, a.w * w4.w)));
        }

        // butterfly stages 16, 8, 4
        #pragma unroll
        for (int s2 = 16; s2 >= 4; s2 >>= 1) {
            #pragma unroll
            for (int k = 0; k < 8; k++)
                d[k] += __shfl_xor_sync(0xFFFFFFFFu, d[k], s2);
        }
        const int grp = lane >> 2;
        float v = d[0];
        v = (grp == 1) ? d[1] : v;
        v = (grp == 2) ? d[2] : v;
        v = (grp == 3) ? d[3] : v;
        v = (grp == 4) ? d[4] : v;
        v = (grp == 5) ? d[5] : v;
        v = (grp == 6) ? d[6] : v;
        v = (grp == 7) ? d[7] : v;
        v += __shfl_xor_sync(0xFFFFFFFFu, v, 1);
        v += __shfl_xor_sync(0xFFFFFFFFu, v, 2);
        if ((lane & 3) == 0)
            s_sc[warp * 128 + it * 8 + grp] = v;

        // refill the slot we just consumed (group it+STAGES)
        if (it + STAGES < 16) {
            const float* gp = base + (size_t)(it + STAGES) * 8 * RDIM + lane * 4;
            const uint32_t dst = sbase + slot * 4096 + lane * 16;
            #pragma unroll
            for (int k = 0; k < 8; k++)
                cp16(dst + k * 512, gp + k * RDIM);
        }
        asm volatile("cp.async.commit_group;" ::: "memory");

        if (++slot == STAGES) slot = 0;
    }
    __syncthreads();

    // ---- masked softmax over the 1024 scores ----
    const float b = att_b[0];

    float vals[4];
    unsigned mbits = 0;
    float vmax = -1e30f;
    #pragma unroll
    for (int k = 0; k < 4; k++) {
        const int j = tid + k * 256;
        const bool m = (s_nei[j] > 0);
        if (m) mbits |= (1u << k);
        const float v = m ? (s_sc[j] + b) : -1e-6f;
        vals[k] = v;
        vmax = fmaxf(vmax, v);
    }
    #pragma unroll
    for (int s = 16; s; s >>= 1)
        vmax = fmaxf(vmax, __shfl_xor_sync(0xFFFFFFFFu, vmax, s));
    if (lane == 0) s_red[warp] = vmax;
    __syncthreads();
    {
        float t = s_red[lane & 7];
        #pragma unroll
        for (int s = 4; s; s >>= 1)
            t = fmaxf(t, __shfl_xor_sync(0xFFFFFFFFu, t, s));
        vmax = t;
    }

    float vsum = 0.0f;
    #pragma unroll
    for (int k = 0; k < 4; k++) {
        const float e = __expf(vals[k] - vmax);
        vals[k] = e;
        vsum += e;
    }
    #pragma unroll
    for (int s = 16; s; s >>= 1)
        vsum += __shfl_xor_sync(0xFFFFFFFFu, vsum, s);
    __syncthreads();
    if (lane == 0) s_red[8 + warp] = vsum;
    __syncthreads();
    {
        float t = s_red[8 + (lane & 7)];
        #pragma unroll
        for (int s = 4; s; s >>= 1)
            t += __shfl_xor_sync(0xFFFFFFFFu, t, s);
        vsum = t;
    }
    const float inv = 1.0f / vsum;

    float* wrow = wout + (size_t)i * P;
    #pragma unroll
    for (int k = 0; k < 4; k++) {
        const int j = tid + k * 256;
        wrow[j] = ((mbits >> k) & 1u) ? vals[k] * inv : 0.0f;
    }
}

// =====================================================================
// Kernel B1: tf32 tensor-core split-K GEMM, software-pipelined.
// Grid 128 = 32 i-tiles x 4 j-splits; 256 threads (8 warps).
// W (32x256) staged once; H staged in 64x128 chunks, double-buffered,
// next chunk prefetched into registers before the mma section.
// =====================================================================
#define WSTRIDE 260
#define HSTRIDE 136
#define KCHUNK  64
#define NCHUNKS 4
#define B1_SMEM ((ITILE * WSTRIDE + 2 * KCHUNK * HSTRIDE) * 4)

__device__ __forceinline__ uint32_t f2tf32(float f) {
    uint32_t r;
    asm("cvt.rna.tf32.f32 %0, %1;" : "=r"(r) : "f"(f));
    return r;
}

__device__ __forceinline__ void mma_tf32(float d[4],
                                         uint32_t a0, uint32_t a1,
                                         uint32_t a2, uint32_t a3,
                                         uint32_t b0, uint32_t b1)
{
    asm("mma.sync.aligned.m16n8k8.row.col.f32.tf32.tf32.f32 "
        "{%0,%1,%2,%3}, {%4,%5,%6,%7}, {%8,%9}, {%0,%1,%2,%3};"
        : "+f"(d[0]), "+f"(d[1]), "+f"(d[2]), "+f"(d[3])
        : "r"(a0), "r"(a1), "r"(a2), "r"(a3), "r"(b0), "r"(b1));
}

__global__ __launch_bounds__(256)
void si_gemm_tc_kernel(const float* __restrict__ hidden,
                       const float* __restrict__ wsrc,
                       float*       __restrict__ part)
{
    extern __shared__ uint32_t smem_u[];
    uint32_t* s_w = smem_u;                          // [ITILE * WSTRIDE]
    uint32_t* s_h = smem_u + ITILE * WSTRIDE;        // [2 * KCHUNK * HSTRIDE]

    const int tid  = threadIdx.x;
    const int lane = tid & 31;
    const int warp = tid >> 5;
    const int it   = blockIdx.x >> 2;                // 0..31
    const int js   = blockIdx.x & 3;                 // 0..3
    const int i0   = it * ITILE;
    const int jb   = js * 256;

    // ---- issue W loads and H chunk-0 loads together ----
    float4 wv[8];
    #pragma unroll
    for (int t = 0; t < 8; t++) {
        const int idx4 = tid + t * 256;              // 0..2047
        const int r    = idx4 >> 6;
        const int c4   = idx4 & 63;
        wv[t] = *reinterpret_cast<const float4*>(
            &wsrc[(size_t)(i0 + r) * P + jb + c4 * 4]);
    }
    float4 hv[8];
    #pragma unroll
    for (int t = 0; t < 8; t++) {
        const int idx4 = tid + t * 256;
        const int k    = idx4 >> 5;
        const int m4   = idx4 & 31;
        hv[t] = *reinterpret_cast<const float4*>(
            &hidden[(size_t)(jb + k) * MDIM + m4 * 4]);
    }

    // ---- store W (tf32) ----
    #pragma unroll
    for (int t = 0; t < 8; t++) {
        const int idx4 = tid + t * 256;
        const int r    = idx4 >> 6;
        const int c4   = idx4 & 63;
        uint4 u;
        u.x = f2tf32(wv[t].x); u.y = f2tf32(wv[t].y);
        u.z = f2tf32(wv[t].z); u.w = f2tf32(wv[t].w);
        *reinterpret_cast<uint4*>(&s_w[r * WSTRIDE + c4 * 4]) = u;
    }
    // ---- store H chunk 0 (tf32) into buffer 0 ----
    #pragma unroll
    for (int t = 0; t < 8; t++) {
        const int idx4 = tid + t * 256;
        const int k    = idx4 >> 5;
        const int m4   = idx4 & 31;
        uint4 u;
        u.x = f2tf32(hv[t].x); u.y = f2tf32(hv[t].y);
        u.z = f2tf32(hv[t].z); u.w = f2tf32(hv[t].w);
        *reinterpret_cast<uint4*>(&s_h[k * HSTRIDE + m4 * 4]) = u;
    }
    __syncthreads();

    const int g  = lane >> 2;       // groupID 0..7
    const int tg = lane & 3;        // thread-in-group 0..3
    const int mh = warp >> 2;       // m-half 0/1
    const int nb = (warp & 3) * 32; // n-block base

    float d[4][4];
    #pragma unroll
    for (int nt = 0; nt < 4; nt++)
        #pragma unroll
        for (int c = 0; c < 4; c++) d[nt][c] = 0.0f;

    #pragma unroll 1
    for (int kci = 0; kci < NCHUNKS; kci++) {
        const int buf = kci & 1;
        const uint32_t* sh = s_h + buf * (KCHUNK * HSTRIDE);

        // prefetch next chunk into registers (overlaps with mma below)
        if (kci + 1 < NCHUNKS) {
            const int kc1 = (kci + 1) * KCHUNK;
            #pragma unroll
            for (int t = 0; t < 8; t++) {
                const int idx4 = tid + t * 256;
                const int k    = idx4 >> 5;
                const int m4   = idx4 & 31;
                hv[t] = *reinterpret_cast<const float4*>(
                    &hidden[(size_t)(jb + kc1 + k) * MDIM + m4 * 4]);
            }
        }

        // ---- 8 k-steps of m16n8k8 on current buffer ----
        #pragma unroll
        for (int ks = 0; ks < 8; ks++) {
            const int kA = kci * KCHUNK + ks * 8;    // col in s_w
            const int rowA = mh * 16 + g;
            const uint32_t a0 = s_w[(rowA    ) * WSTRIDE + kA + tg    ];
            const uint32_t a1 = s_w[(rowA + 8) * WSTRIDE + kA + tg    ];
            const uint32_t a2 = s_w[(rowA    ) * WSTRIDE + kA + tg + 4];
            const uint32_t a3 = s_w[(rowA + 8) * WSTRIDE + kA + tg + 4];

            const int kH = ks * 8;                   // row in chunk
            #pragma unroll
            for (int nt = 0; nt < 4; nt++) {
                const int n = nb + nt * 8 + g;
                const uint32_t b0 = sh[(kH + tg    ) * HSTRIDE + n];
                const uint32_t b1 = sh[(kH + tg + 4) * HSTRIDE + n];
                mma_tf32(d[nt], a0, a1, a2, a3, b0, b1);
            }
        }
        __syncthreads();   // all reads of the other buffer (prev iter) done

        if (kci + 1 < NCHUNKS) {
            uint32_t* shn = s_h + ((kci + 1) & 1) * (KCHUNK * HSTRIDE);
            #pragma unroll
            for (int t = 0; t < 8; t++) {
                const int idx4 = tid + t * 256;
                const int k    = idx4 >> 5;
                const int m4   = idx4 & 31;
                uint4 u;
                u.x = f2tf32(hv[t].x); u.y = f2tf32(hv[t].y);
                u.z = f2tf32(hv[t].z); u.w = f2tf32(hv[t].w);
                *reinterpret_cast<uint4*>(&shn[k * HSTRIDE + m4 * 4]) = u;
            }
            __syncthreads();
        }
    }

    // ---- epilogue: write D fragments to split-K partial buffer ----
    {
        float* pb = part + (size_t)js * P * MDIM;
        const int r0 = i0 + mh * 16 + g;
        #pragma unroll
        for (int nt = 0; nt < 4; nt++) {
            const int col = nb + nt * 8 + 2 * tg;
            float2 lo; lo.x = d[nt][0]; lo.y = d[nt][1];
            float2 hi; hi.x = d[nt][2]; hi.y = d[nt][3];
            *reinterpret_cast<float2*>(&pb[(size_t)(r0    ) * MDIM + col]) = lo;
            *reinterpret_cast<float2*>(&pb[(size_t)(r0 + 8) * MDIM + col]) = hi;
        }
    }
}

// =====================================================================
// Kernel B2: reduce 4 split-K partials -> out. 131072 floats = 32768 f4.
// =====================================================================
__global__ __launch_bounds__(256)
void si_gemm_reduce_kernel(const float* __restrict__ part,
                           float*       __restrict__ out)
{
    const int e4 = blockIdx.x * 256 + threadIdx.x;   // 0..32767
    const float4* p4 = reinterpret_cast<const float4*>(part);
    const float4 a = p4[0 * 32768 + e4];
    const float4 b = p4[1 * 32768 + e4];
    const float4 c = p4[2 * 32768 + e4];
    const float4 e = p4[3 * 32768 + e4];
    float4 s;
    s.x = (a.x + b.x) + (c.x + e.x);
    s.y = (a.y + b.y) + (c.y + e.y);
    s.z = (a.z + b.z) + (c.z + e.z);
    s.w = (a.w + b.w) + (c.w + e.w);
    reinterpret_cast<float4*>(out)[e4] = s;
}

extern "C" void kernel_launch(void* const* d_in, const int* in_sizes, int n_in,
                              void* d_out, int out_size)
{
    (void)in_sizes; (void)n_in; (void)out_size;
    const float* hidden = (const float*)d_in[0];   // [1024,128]
    const float* rela   = (const float*)d_in[1];   // [1024,1024,128]
    // d_in[2] = corr_index : unused
    const int*   nei    = (const int*)  d_in[3];   // [1024,1024]
    const float* att_w  = (const float*)d_in[4];   // [128]
    const float* att_b  = (const float*)d_in[5];   // [1]
    float* out = (float*)d_out;                    // [1024,128] f32

    float* wbuf;  cudaGetSymbolAddress((void**)&wbuf, g_wbuf);
    float* pbuf;  cudaGetSymbolAddress((void**)&pbuf, g_part);

    cudaFuncSetAttribute(si_row_kernel,
                         cudaFuncAttributeMaxDynamicSharedMemorySize, A_SMEM_BYTES);
    cudaFuncSetAttribute(si_gemm_tc_kernel,
                         cudaFuncAttributeMaxDynamicSharedMemorySize, B1_SMEM);

    si_row_kernel<<<P, 256, A_SMEM_BYTES>>>(rela, nei, att_w, att_b, wbuf);
    si_gemm_tc_kernel<<<(P / ITILE) * JSPLIT, 256, B1_SMEM>>>(hidden, wbuf, pbuf);
    si_gemm_reduce_kernel<<<P * MDIM / 4 / 256, 256>>>(pbuf, out);
}